// round 5
// baseline (speedup 1.0000x reference)
#include <cuda_runtime.h>

#define MAXN 128              // max gt boxes per image
#define ENT  (MAXN * 4)       // max bin-list entries per batch (<=4 bins per box)
#define NBX  4                // bins per dimension
#define NBIN (NBX * NBX)
#define BINW 256.0f
#define NKEY 144              // anchor bin-range buckets
#define MAXB 16               // max batch

// Scratch (device globals; no allocation allowed)
__device__ unsigned long long g_pbest[MAXB * MAXN];  // per-(b,n) best (iou, ~anchor)
__device__ unsigned long long g_abest[1 << 20];      // per-(b,a) (iou, box idx)
__device__ int                g_winner[1 << 20];     // per-(b,a) segment_max winner
__device__ float              g_miou[MAXB * MAXN];   // per-(b,n) max iou over anchors
__device__ int    g_acnt[NKEY];                      // anchor bucket counts
__device__ int    g_aofs[NKEY];                      // bucket offsets (cursor in scatter)
__device__ int    g_sorted[1 << 17];                 // anchors sorted by bucket
__device__ int    g_bofs[MAXB * (NBIN + 1)];         // per-batch box-bin prefix offsets
__device__ float4 g_bbox[MAXB * ENT];                // compacted per-bin box rects
__device__ float  g_barea[MAXB * ENT];               // compacted per-bin box areas
__device__ int    g_bidx[MAXB * ENT];                // compacted per-bin box indices

__device__ __forceinline__ int binclamp(float v) {
    int i = (int)(fmaxf(v, 0.f) * (1.0f / BINW));
    return (i > NBX - 1) ? NBX - 1 : i;
}

__device__ __forceinline__ void anchor_rect(float4 c, float& ax1, float& ay1,
                                            float& ax2, float& ay2) {
    ax1 = c.x - c.z * 0.5f;  ay1 = c.y - c.w * 0.5f;
    ax2 = c.x + c.z * 0.5f;  ay2 = c.y + c.w * 0.5f;
}

__device__ __forceinline__ int anchor_key(float4 c) {
    float ax1, ay1, ax2, ay2;
    anchor_rect(c, ax1, ay1, ax2, ay2);
    int x0 = binclamp(ax1), x1 = binclamp(ax2);
    int y0 = binclamp(ay1), y1 = binclamp(ay2);
    return (y0 * 3 + (y1 - y0)) * 12 + (x0 * 3 + (x1 - x0));
}

// K0: per-batch box binning (compacted lists) + g_pbest init; block 0 zeros g_acnt.
__global__ void k_bins(const float4* __restrict__ bboxes, int N)
{
    __shared__ int scnt[NBIN], sofs[NBIN + 1], scur[NBIN];
    const int b = blockIdx.x, tid = threadIdx.x;
    if (b == 0) for (int i = tid; i < NKEY; i += blockDim.x) g_acnt[i] = 0;
    if (tid < NBIN) scnt[tid] = 0;
    __syncthreads();

    float4 bb = make_float4(0, 0, 0, 0);
    int bx0 = 0, bx1 = -1, by0 = 0, by1 = -1;
    if (tid < N) {
        bb = bboxes[b * N + tid];
        bx0 = binclamp(bb.x); bx1 = binclamp(bb.z);
        by0 = binclamp(bb.y); by1 = binclamp(bb.w);
        for (int y = by0; y <= by1; y++)
            for (int x = bx0; x <= bx1; x++)
                atomicAdd(&scnt[y * NBX + x], 1);
        // init per-box best key: iou=0, anchor=0 (complement 0xFFFFFFFF) —
        // matches reference argmax(all-zero column) = anchor 0.
        g_pbest[b * N + tid] = 0xFFFFFFFFull;
    }
    __syncthreads();
    if (tid == 0) {
        int run = 0;
        for (int i = 0; i < NBIN; i++) { sofs[i] = run; run += scnt[i]; }
        sofs[NBIN] = run;
    }
    __syncthreads();
    if (tid < NBIN) scur[tid] = sofs[tid];
    if (tid <= NBIN) g_bofs[b * (NBIN + 1) + tid] = sofs[tid];
    __syncthreads();
    if (tid < N) {
        float area = (bb.z - bb.x) * (bb.w - bb.y);
        for (int y = by0; y <= by1; y++)
            for (int x = bx0; x <= bx1; x++) {
                int slot = atomicAdd(&scur[y * NBX + x], 1);
                g_bbox[b * ENT + slot]  = bb;
                g_barea[b * ENT + slot] = area;
                g_bidx[b * ENT + slot]  = tid;
            }
    }
}

// S1: histogram anchors into 144 bin-range buckets.
__global__ void k_hist(const float4* __restrict__ anchors, int A)
{
    __shared__ int sh[NKEY];
    const int tid = threadIdx.x;
    for (int i = tid; i < NKEY; i += blockDim.x) sh[i] = 0;
    __syncthreads();
    int a = blockIdx.x * blockDim.x + tid;
    if (a < A) atomicAdd(&sh[anchor_key(anchors[a])], 1);
    __syncthreads();
    for (int i = tid; i < NKEY; i += blockDim.x)
        if (sh[i]) atomicAdd(&g_acnt[i], sh[i]);
}

// S2: serial exclusive scan of 144 buckets.
__global__ void k_scan()
{
    int run = 0;
    for (int i = 0; i < NKEY; i++) { g_aofs[i] = run; run += g_acnt[i]; }
}

// S3: scatter anchor ids bucket-sorted (order within bucket arbitrary — all
// downstream results are order-invariant max/argmax-by-key).
__global__ void k_scatter(const float4* __restrict__ anchors, int A)
{
    int a = blockIdx.x * blockDim.x + threadIdx.x;
    if (a >= A) return;
    int pos = atomicAdd(&g_aofs[anchor_key(anchors[a])], 1);
    g_sorted[pos] = a;
}

// K1: matched work — each thread = one (bucket-sorted) anchor; iterate only
// boxes in bins the anchor rect touches. Per-anchor argmax + per-box RED.MAX.
__global__ void __launch_bounds__(256)
k_match(const float4* __restrict__ anchors, int A, int N)
{
    __shared__ float4 sbb[ENT];
    __shared__ float  sar[ENT];
    __shared__ int    sdx[ENT];
    __shared__ int    sofs[NBIN + 1];

    const int b = blockIdx.y, tid = threadIdx.x;
    if (tid <= NBIN) sofs[tid] = g_bofs[b * (NBIN + 1) + tid];
    __syncthreads();
    const int E = sofs[NBIN];
    for (int i = tid; i < E; i += 256) {
        sbb[i] = g_bbox[b * ENT + i];
        sar[i] = g_barea[b * ENT + i];
        sdx[i] = g_bidx[b * ENT + i];
    }
    __syncthreads();

    const int aidx = blockIdx.x * 256 + tid;
    if (aidx >= A) return;
    const int sid = g_sorted[aidx];

    float4 c = __ldg(&anchors[sid]);
    float ax1, ay1, ax2, ay2;
    anchor_rect(c, ax1, ay1, ax2, ay2);
    const float areaA = (ax2 - ax1) * (ay2 - ay1);   // reference order
    const int x0 = binclamp(ax1), x1 = binclamp(ax2);
    const int y0 = binclamp(ay1), y1 = binclamp(ay2);

    float bestI = 0.f;                 // pruned pairs are exactly 0 in reference
    int   bestN = 0;
    const unsigned nsid = 0xFFFFFFFFu - (unsigned)sid;
    unsigned long long* pb = g_pbest + b * N;

    for (int y = y0; y <= y1; y++)
        for (int x = x0; x <= x1; x++) {
            const int bin = y * NBX + x;
            const int sEnd = sofs[bin + 1];
            for (int s = sofs[bin]; s < sEnd; s++) {
                float4 bb = sbb[s];
                float ltx = fmaxf(ax1, bb.x), lty = fmaxf(ay1, bb.y);
                float rbx = fminf(ax2, bb.z), rby = fminf(ay2, bb.w);
                float w = fmaxf(rbx - ltx, 0.f), h = fmaxf(rby - lty, 0.f);
                float inter = w * h;
                float iou = __fdividef(inter, areaA + sar[s] - inter);
                int n = sdx[s];
                if (iou > bestI) { bestI = iou; bestN = n; }
                if (iou > 0.f)
                    atomicMax(&pb[n],
                        ((unsigned long long)__float_as_uint(iou) << 32) | nsid);
            }
        }

    const size_t base = (size_t)b * A + sid;
    g_winner[base] = -1;
    g_abest[base]  = ((unsigned long long)__float_as_uint(bestI) << 32) |
                     (unsigned)bestN;
}

// K2: per-(b,n) unpack best key -> g_miou + segment_max winner scatter.
__global__ void k_box(int A, int N, int total)
{
    int bn = blockIdx.x * blockDim.x + threadIdx.x;
    if (bn >= total) return;
    unsigned long long key = g_pbest[bn];
    float miou = __uint_as_float((unsigned)(key >> 32));
    int   idx  = (int)(0xFFFFFFFFu - (unsigned)key);
    g_miou[bn] = miou;
    int b = bn / N, n = bn - b * N;
    atomicMax(&g_winner[(size_t)b * A + idx], n);
}

// K3: epilogue per anchor: winner override, scores, conf scatter, delta encode.
__global__ void __launch_bounds__(256)
k_phase3(const float4* __restrict__ anchors, const float4* __restrict__ bboxes,
         const int* __restrict__ labels,
         const float* __restrict__ enc_mean, const float* __restrict__ enc_std,
         const float* __restrict__ thr_ptr,
         float* __restrict__ out_conf, float4* __restrict__ out_delta,
         int A, int N, int C)
{
    __shared__ float4 sbox[MAXN];
    __shared__ int    slab[MAXN];
    __shared__ float  smiou[MAXN];

    const int b = blockIdx.y, tid = threadIdx.x;
    for (int n = tid; n < N; n += 256) {
        sbox[n]  = bboxes[b * N + n];
        slab[n]  = labels[b * N + n];
        smiou[n] = g_miou[b * N + n];
    }
    __syncthreads();

    const int a = blockIdx.x * 256 + tid;
    if (a >= A) return;

    const float thr = __ldg(thr_ptr);
    unsigned long long ab = g_abest[(size_t)b * A + a];
    float miou = __uint_as_float((unsigned)(ab >> 32));
    int   idx  = (int)(unsigned)ab;

    int w = g_winner[(size_t)b * A + a];
    if (w >= 0) { idx = w; miou = smiou[w]; }

    float den = fmaxf(smiou[idx], thr);
    if (miou < thr * 0.5f) miou = 0.f;
    float score = miou / den;

    int lab = slab[idx];
    if (lab <= 0) { score = 0.f; lab = 0; }

    const size_t base = (size_t)b * A + a;
    for (int c = 0; c < C; c++)
        out_conf[base * C + c] = (lab == c + 1) ? score : 0.f;

    float4 m   = sbox[idx];
    float4 anc = anchors[a];
    float mcx = (m.x + m.z) * 0.5f, mcy = (m.y + m.w) * 0.5f;
    float mw  = m.z - m.x,          mh  = m.w - m.y;
    float d0 = (mcx - anc.x) / anc.z;
    float d1 = (mcy - anc.y) / anc.w;
    float d2 = logf(mw / anc.z);
    float d3 = logf(mh / anc.w);
    float4 dv;
    dv.x = (d0 - __ldg(&enc_mean[0])) / __ldg(&enc_std[0]);
    dv.y = (d1 - __ldg(&enc_mean[1])) / __ldg(&enc_std[1]);
    dv.z = (d2 - __ldg(&enc_mean[2])) / __ldg(&enc_std[2]);
    dv.w = (d3 - __ldg(&enc_mean[3])) / __ldg(&enc_std[3]);
    out_delta[base] = dv;
}

extern "C" void kernel_launch(void* const* d_in, const int* in_sizes, int n_in,
                              void* d_out, int out_size)
{
    const float* anchors = (const float*)d_in[0];
    const int*   labels  = (const int*)d_in[1];
    const float* bboxes  = (const float*)d_in[2];
    const float* emean   = (const float*)d_in[3];
    const float* estd    = (const float*)d_in[4];
    const float* thr     = (const float*)d_in[5];

    const int A  = in_sizes[0] / 4;          // anchors [A,4]
    const int BN = in_sizes[1];              // labels [B,N]
    int B = out_size / (5 * A);
    if (B <= 0) B = 1;
    const int N = BN / B;
    const int C = (int)((long)out_size / ((long)B * A)) - 4;

    const float4* anc4 = (const float4*)anchors;
    const float4* box4 = (const float4*)bboxes;

    k_bins<<<B, 128>>>(box4, N);
    k_hist<<<(A + 255) / 256, 256>>>(anc4, A);
    k_scan<<<1, 1>>>();
    k_scatter<<<(A + 255) / 256, 256>>>(anc4, A);

    dim3 gm((A + 255) / 256, B);
    k_match<<<gm, 256>>>(anc4, A, N);
    k_box<<<(B * N + 255) / 256, 256>>>(A, N, B * N);

    float*  out_conf  = (float*)d_out;
    float4* out_delta = (float4*)((float*)d_out + (size_t)B * A * C);
    dim3 g3((A + 255) / 256, B);
    k_phase3<<<g3, 256>>>(anc4, box4, labels, emean, estd, thr,
                          out_conf, out_delta, A, N, C);
}

// round 6
// speedup vs baseline: 5.9955x; 5.9955x over previous
#include <cuda_runtime.h>

#define TPB 128
#define APT 4                 // anchors per thread
#define CHUNK (TPB * APT)     // anchors per block = 512
#define NW   (TPB / 32)       // warps per block
#define MAXN 128              // max gt boxes per image supported
#define MAXB 16               // max batch

// Scratch (device globals; no allocation allowed)
__device__ unsigned long long g_pbest[MAXB * MAXN];  // per-(b,n) best (iou, ~anchor)
__device__ unsigned long long g_abest[1 << 20];      // per-(b,a) packed (iou, box idx)
__device__ int                g_winner[1 << 20];     // per-(b,a) segment_max winner
__device__ float              g_miou[MAXB * MAXN];   // per-(b,n) max iou over anchors

// K0: reset per-box best keys. iou=0, anchor=0 (stored complemented) — matches
// reference argmax over an all-zero column (= anchor 0).
__global__ void k_init(int total)
{
    int i = blockIdx.x * blockDim.x + threadIdx.x;
    if (i < total) g_pbest[i] = 0xFFFFFFFFull;
}

// K1: for each (batch, 512-anchor chunk): compute all IoUs vs N boxes once.
//  - per-anchor best (axis=1 argmax, strict > = first occurrence) -> g_abest
//  - per-box warp-best (axis=0 argmax candidate, tie -> lowest anchor) -> RED.MAX
//  - init g_winner = -1
__global__ void __launch_bounds__(TPB)
k_phase1(const float4* __restrict__ anchors, const float4* __restrict__ bboxes,
         int A, int N)
{
    __shared__ float4 sbox[MAXN];
    __shared__ float  sarea[MAXN];

    const int b = blockIdx.y, chunk = blockIdx.x, tid = threadIdx.x;
    const int lane = tid & 31;

    for (int n = tid; n < N; n += TPB) {
        float4 bb = bboxes[b * N + n];
        sbox[n] = bb;
        sarea[n] = (bb.z - bb.x) * (bb.w - bb.y);
    }
    __syncthreads();

    // Load APT anchors (stride TPB so within-warp anchor order == lane order)
    float ax1[APT], ay1[APT], ax2[APT], ay2[APT], areaA[APT];
    unsigned aidx[APT];
    bool avalid[APT];
    #pragma unroll
    for (int k = 0; k < APT; k++) {
        int a = chunk * CHUNK + k * TPB + tid;
        aidx[k] = (unsigned)a;
        avalid[k] = (a < A);
        if (avalid[k]) {
            float4 c = anchors[a];
            ax1[k] = c.x - c.z * 0.5f;  ay1[k] = c.y - c.w * 0.5f;
            ax2[k] = c.x + c.z * 0.5f;  ay2[k] = c.y + c.w * 0.5f;
            areaA[k] = (ax2[k] - ax1[k]) * (ay2[k] - ay1[k]);  // reference order
            g_winner[(size_t)b * A + a] = -1;
        } else {
            // dummy: zero extent -> IoU exactly 0 vs any valid box; index larger
            // than every real anchor so it never wins a tie-break.
            ax1[k] = 0.f; ay1[k] = 0.f; ax2[k] = 0.f; ay2[k] = 0.f;
            areaA[k] = 0.f;
        }
    }

    float bestI[APT];
    int   bestN[APT];
    #pragma unroll
    for (int k = 0; k < APT; k++) { bestI[k] = 0.0f; bestN[k] = 0; }

    unsigned long long* pb = g_pbest + b * N;

    #pragma unroll 2
    for (int n = 0; n < N; n++) {
        float4 bb = sbox[n];
        float sa = sarea[n];

        float iou[APT];
        #pragma unroll
        for (int k = 0; k < APT; k++) {
            float ltx = fmaxf(ax1[k], bb.x), lty = fmaxf(ay1[k], bb.y);
            float rbx = fminf(ax2[k], bb.z), rby = fminf(ay2[k], bb.w);
            float w = fmaxf(rbx - ltx, 0.f), h = fmaxf(rby - lty, 0.f);
            float inter = w * h;
            iou[k] = __fdividef(inter, areaA[k] + sa - inter);
        }

        // per-anchor running argmax (strict > = first occurrence)
        #pragma unroll
        for (int k = 0; k < APT; k++)
            if (iou[k] > bestI[k]) { bestI[k] = iou[k]; bestN[k] = n; }

        // merge the APT anchors (strict > keeps earlier = lower anchor index)
        float    mi = iou[0];
        unsigned wa = aidx[0];
        #pragma unroll
        for (int k = 1; k < APT; k++)
            if (iou[k] > mi) { mi = iou[k]; wa = aidx[k]; }

        // warp argmax over anchors for this box: max IoU (uint-monotone, IoU>=0),
        // tie -> min anchor index; lane 0 commits via global RED.MAX.
        unsigned u = __float_as_uint(mi);
        unsigned m = __reduce_max_sync(0xffffffffu, u);
        unsigned cand = (u == m) ? wa : 0xFFFFFFFFu;
        unsigned amin = __reduce_min_sync(0xffffffffu, cand);
        if (lane == 0)
            atomicMax(&pb[n],
                ((unsigned long long)m << 32) | (0xFFFFFFFFu - amin));
    }

    #pragma unroll
    for (int k = 0; k < APT; k++)
        if (avalid[k])
            g_abest[(size_t)b * A + aidx[k]] =
                ((unsigned long long)__float_as_uint(bestI[k]) << 32) |
                (unsigned)bestN[k];
}

// K2: per-(b,n) unpack best key -> g_miou + segment_max winner scatter.
__global__ void k_box(int A, int N, int total)
{
    int bn = blockIdx.x * blockDim.x + threadIdx.x;
    if (bn >= total) return;
    unsigned long long key = g_pbest[bn];
    float miou = __uint_as_float((unsigned)(key >> 32));
    int   idx  = (int)(0xFFFFFFFFu - (unsigned)key);
    g_miou[bn] = miou;
    int b = bn / N, n = bn - b * N;
    atomicMax(&g_winner[(size_t)b * A + idx], n);
}

// K3: epilogue per anchor: winner override, scores, conf scatter, delta encode.
__global__ void __launch_bounds__(256)
k_phase3(const float4* __restrict__ anchors, const float4* __restrict__ bboxes,
         const int* __restrict__ labels,
         const float* __restrict__ enc_mean, const float* __restrict__ enc_std,
         const float* __restrict__ thr_ptr,
         float* __restrict__ out_conf, float4* __restrict__ out_delta,
         int A, int N, int C)
{
    __shared__ float4 sbox[MAXN];
    __shared__ int    slab[MAXN];
    __shared__ float  smiou[MAXN];

    const int b = blockIdx.y, tid = threadIdx.x;
    for (int n = tid; n < N; n += 256) {
        sbox[n]  = bboxes[b * N + n];
        slab[n]  = labels[b * N + n];
        smiou[n] = g_miou[b * N + n];
    }
    __syncthreads();

    const int a = blockIdx.x * 256 + tid;
    if (a >= A) return;

    const float thr = __ldg(thr_ptr);
    unsigned long long ab = g_abest[(size_t)b * A + a];
    float miou = __uint_as_float((unsigned)(ab >> 32));
    int   idx  = (int)(unsigned)ab;

    int w = g_winner[(size_t)b * A + a];
    if (w >= 0) { idx = w; miou = smiou[w]; }

    float den = fmaxf(smiou[idx], thr);
    if (miou < thr * 0.5f) miou = 0.f;
    float score = miou / den;

    int lab = slab[idx];
    if (lab <= 0) { score = 0.f; lab = 0; }

    const size_t base = (size_t)b * A + a;
    for (int c = 0; c < C; c++)
        out_conf[base * C + c] = (lab == c + 1) ? score : 0.f;

    float4 m   = sbox[idx];
    float4 anc = anchors[a];
    float mcx = (m.x + m.z) * 0.5f, mcy = (m.y + m.w) * 0.5f;
    float mw  = m.z - m.x,          mh  = m.w - m.y;
    float d0 = (mcx - anc.x) / anc.z;
    float d1 = (mcy - anc.y) / anc.w;
    float d2 = logf(mw / anc.z);
    float d3 = logf(mh / anc.w);
    float4 dv;
    dv.x = (d0 - __ldg(&enc_mean[0])) / __ldg(&enc_std[0]);
    dv.y = (d1 - __ldg(&enc_mean[1])) / __ldg(&enc_std[1]);
    dv.z = (d2 - __ldg(&enc_mean[2])) / __ldg(&enc_std[2]);
    dv.w = (d3 - __ldg(&enc_mean[3])) / __ldg(&enc_std[3]);
    out_delta[base] = dv;
}

extern "C" void kernel_launch(void* const* d_in, const int* in_sizes, int n_in,
                              void* d_out, int out_size)
{
    const float* anchors = (const float*)d_in[0];
    const int*   labels  = (const int*)d_in[1];
    const float* bboxes  = (const float*)d_in[2];
    const float* emean   = (const float*)d_in[3];
    const float* estd    = (const float*)d_in[4];
    const float* thr     = (const float*)d_in[5];

    const int A  = in_sizes[0] / 4;          // anchors [A,4]
    const int BN = in_sizes[1];              // labels [B,N]
    int B = out_size / (5 * A);
    if (B <= 0) B = 1;
    const int N = BN / B;
    const int C = (int)((long)out_size / ((long)B * A)) - 4;

    const float4* anc4 = (const float4*)anchors;
    const float4* box4 = (const float4*)bboxes;

    k_init<<<(B * N + 1023) / 1024, 1024>>>(B * N);

    const int numChunks = (A + CHUNK - 1) / CHUNK;
    dim3 grid1(numChunks, B);
    k_phase1<<<grid1, TPB>>>(anc4, box4, A, N);

    k_box<<<(B * N + 255) / 256, 256>>>(A, N, B * N);

    float*  out_conf  = (float*)d_out;
    float4* out_delta = (float4*)((float*)d_out + (size_t)B * A * C);
    dim3 g3((A + 255) / 256, B);
    k_phase3<<<g3, 256>>>(anc4, box4, labels, emean, estd, thr,
                          out_conf, out_delta, A, N, C);
}

// round 7
// speedup vs baseline: 6.4079x; 1.0688x over previous
#include <cuda_runtime.h>

#define TPB 128
#define APT 4                 // anchors per thread
#define CHUNK (TPB * APT)     // anchors per block = 512
#define MAXN 128              // max gt boxes per image supported
#define MAXB 16               // max batch

// Scratch (device globals; no allocation allowed)
__device__ unsigned long long g_pbest[MAXB * MAXN];  // per-(b,n) best (iou, ~anchor)
__device__ unsigned long long g_abest[1 << 20];      // per-(b,a) packed (iou, box idx)
__device__ int                g_winner[1 << 20];     // per-(b,a) segment_max winner
__device__ float              g_miou[MAXB * MAXN];   // per-(b,n) max iou over anchors

// K0: reset per-box best keys. iou=0, anchor=0 (stored complemented) — matches
// reference argmax over an all-zero column (= anchor 0).
__global__ void k_init(int total)
{
    int i = blockIdx.x * blockDim.x + threadIdx.x;
    if (i < total) g_pbest[i] = 0xFFFFFFFFull;
}

// K1: for each (batch, 512-anchor chunk): compute all IoUs vs N boxes once.
//  - per-anchor best (axis=1 argmax) -> g_abest
//  - per-box warp-best (axis=0 argmax candidate, tie -> lowest anchor) -> RED.MAX
//    Box iteration is STAGGERED per block (start = chunk % N) so concurrent
//    blocks hit different g_pbest addresses -> no L2 atomic serialization.
//  - init g_winner = -1
__global__ void __launch_bounds__(TPB)
k_phase1(const float4* __restrict__ anchors, const float4* __restrict__ bboxes,
         int A, int N)
{
    __shared__ float4 sbox[MAXN];
    __shared__ float  sarea[MAXN];

    const int b = blockIdx.y, chunk = blockIdx.x, tid = threadIdx.x;
    const int lane = tid & 31;

    for (int n = tid; n < N; n += TPB) {
        float4 bb = bboxes[b * N + n];
        sbox[n] = bb;
        sarea[n] = (bb.z - bb.x) * (bb.w - bb.y);
    }
    __syncthreads();

    // Load APT anchors (stride TPB so within-warp anchor order == lane order)
    float ax1[APT], ay1[APT], ax2[APT], ay2[APT], areaA[APT];
    unsigned aidx[APT];
    bool avalid[APT];
    #pragma unroll
    for (int k = 0; k < APT; k++) {
        int a = chunk * CHUNK + k * TPB + tid;
        aidx[k] = (unsigned)a;
        avalid[k] = (a < A);
        if (avalid[k]) {
            float4 c = anchors[a];
            ax1[k] = c.x - c.z * 0.5f;  ay1[k] = c.y - c.w * 0.5f;
            ax2[k] = c.x + c.z * 0.5f;  ay2[k] = c.y + c.w * 0.5f;
            areaA[k] = (ax2[k] - ax1[k]) * (ay2[k] - ay1[k]);  // reference order
            g_winner[(size_t)b * A + a] = -1;
        } else {
            // dummy: zero extent -> IoU exactly 0 vs any valid box; index larger
            // than every real anchor so it never wins a tie-break.
            ax1[k] = 0.f; ay1[k] = 0.f; ax2[k] = 0.f; ay2[k] = 0.f;
            areaA[k] = 0.f;
        }
    }

    float bestI[APT];
    int   bestN[APT];
    #pragma unroll
    for (int k = 0; k < APT; k++) { bestI[k] = 0.0f; bestN[k] = 0; }

    unsigned long long* pb = g_pbest + b * N;

    int n = chunk % N;                 // staggered start
    for (int it = 0; it < N; it++) {
        float4 bb = sbox[n];
        float sa = sarea[n];

        float iou[APT];
        #pragma unroll
        for (int k = 0; k < APT; k++) {
            float ltx = fmaxf(ax1[k], bb.x), lty = fmaxf(ay1[k], bb.y);
            float rbx = fminf(ax2[k], bb.z), rby = fminf(ay2[k], bb.w);
            float w = fmaxf(rbx - ltx, 0.f), h = fmaxf(rby - lty, 0.f);
            float inter = w * h;
            iou[k] = __fdividef(inter, areaA[k] + sa - inter);
        }

        // per-anchor running argmax. Strict > + 0-init: zeros never update so
        // all-zero rows give argmax 0; positive bit-equal ties are measure-zero,
        // so the rotated visit order matches JAX argmax.
        #pragma unroll
        for (int k = 0; k < APT; k++)
            if (iou[k] > bestI[k]) { bestI[k] = iou[k]; bestN[k] = n; }

        // merge the APT anchors (strict > keeps earlier = lower anchor index)
        float    mi = iou[0];
        unsigned wa = aidx[0];
        #pragma unroll
        for (int k = 1; k < APT; k++)
            if (iou[k] > mi) { mi = iou[k]; wa = aidx[k]; }

        // warp argmax over anchors for this box: max IoU (uint-monotone, IoU>=0),
        // tie -> min anchor index; lane 0 commits via global RED.MAX.
        unsigned u = __float_as_uint(mi);
        unsigned m = __reduce_max_sync(0xffffffffu, u);
        unsigned cand = (u == m) ? wa : 0xFFFFFFFFu;
        unsigned amin = __reduce_min_sync(0xffffffffu, cand);
        if (lane == 0 && m != 0u)      // m==0 is the init value; skip RED
            atomicMax(&pb[n],
                ((unsigned long long)m << 32) | (0xFFFFFFFFu - amin));

        if (++n == N) n = 0;
    }

    #pragma unroll
    for (int k = 0; k < APT; k++)
        if (avalid[k])
            g_abest[(size_t)b * A + aidx[k]] =
                ((unsigned long long)__float_as_uint(bestI[k]) << 32) |
                (unsigned)bestN[k];
}

// K2: per-(b,n) unpack best key -> g_miou + segment_max winner scatter.
__global__ void k_box(int A, int N, int total)
{
    int bn = blockIdx.x * blockDim.x + threadIdx.x;
    if (bn >= total) return;
    unsigned long long key = g_pbest[bn];
    float miou = __uint_as_float((unsigned)(key >> 32));
    int   idx  = (int)(0xFFFFFFFFu - (unsigned)key);
    g_miou[bn] = miou;
    int b = bn / N, n = bn - b * N;
    atomicMax(&g_winner[(size_t)b * A + idx], n);
}

// K3: epilogue per anchor: winner override, scores, conf scatter, delta encode.
__global__ void __launch_bounds__(256)
k_phase3(const float4* __restrict__ anchors, const float4* __restrict__ bboxes,
         const int* __restrict__ labels,
         const float* __restrict__ enc_mean, const float* __restrict__ enc_std,
         const float* __restrict__ thr_ptr,
         float* __restrict__ out_conf, float4* __restrict__ out_delta,
         int A, int N, int C)
{
    __shared__ float4 sbox[MAXN];
    __shared__ int    slab[MAXN];
    __shared__ float  smiou[MAXN];

    const int b = blockIdx.y, tid = threadIdx.x;
    for (int n = tid; n < N; n += 256) {
        sbox[n]  = bboxes[b * N + n];
        slab[n]  = labels[b * N + n];
        smiou[n] = g_miou[b * N + n];
    }
    __syncthreads();

    const int a = blockIdx.x * 256 + tid;
    if (a >= A) return;

    const float thr = __ldg(thr_ptr);
    unsigned long long ab = g_abest[(size_t)b * A + a];
    float miou = __uint_as_float((unsigned)(ab >> 32));
    int   idx  = (int)(unsigned)ab;

    int w = g_winner[(size_t)b * A + a];
    if (w >= 0) { idx = w; miou = smiou[w]; }

    float den = fmaxf(smiou[idx], thr);
    if (miou < thr * 0.5f) miou = 0.f;
    float score = miou / den;

    int lab = slab[idx];
    if (lab <= 0) { score = 0.f; lab = 0; }

    const size_t base = (size_t)b * A + a;
    for (int c = 0; c < C; c++)
        out_conf[base * C + c] = (lab == c + 1) ? score : 0.f;

    float4 m   = sbox[idx];
    float4 anc = anchors[a];
    float mcx = (m.x + m.z) * 0.5f, mcy = (m.y + m.w) * 0.5f;
    float mw  = m.z - m.x,          mh  = m.w - m.y;
    float d0 = (mcx - anc.x) / anc.z;
    float d1 = (mcy - anc.y) / anc.w;
    float d2 = __logf(mw / anc.z);
    float d3 = __logf(mh / anc.w);
    float4 dv;
    dv.x = (d0 - __ldg(&enc_mean[0])) / __ldg(&enc_std[0]);
    dv.y = (d1 - __ldg(&enc_mean[1])) / __ldg(&enc_std[1]);
    dv.z = (d2 - __ldg(&enc_mean[2])) / __ldg(&enc_std[2]);
    dv.w = (d3 - __ldg(&enc_mean[3])) / __ldg(&enc_std[3]);
    out_delta[base] = dv;
}

extern "C" void kernel_launch(void* const* d_in, const int* in_sizes, int n_in,
                              void* d_out, int out_size)
{
    const float* anchors = (const float*)d_in[0];
    const int*   labels  = (const int*)d_in[1];
    const float* bboxes  = (const float*)d_in[2];
    const float* emean   = (const float*)d_in[3];
    const float* estd    = (const float*)d_in[4];
    const float* thr     = (const float*)d_in[5];

    const int A  = in_sizes[0] / 4;          // anchors [A,4]
    const int BN = in_sizes[1];              // labels [B,N]
    int B = out_size / (5 * A);
    if (B <= 0) B = 1;
    const int N = BN / B;
    const int C = (int)((long)out_size / ((long)B * A)) - 4;

    const float4* anc4 = (const float4*)anchors;
    const float4* box4 = (const float4*)bboxes;

    k_init<<<(B * N + 1023) / 1024, 1024>>>(B * N);

    const int numChunks = (A + CHUNK - 1) / CHUNK;
    dim3 grid1(numChunks, B);
    k_phase1<<<grid1, TPB>>>(anc4, box4, A, N);

    k_box<<<(B * N + 255) / 256, 256>>>(A, N, B * N);

    float*  out_conf  = (float*)d_out;
    float4* out_delta = (float4*)((float*)d_out + (size_t)B * A * C);
    dim3 g3((A + 255) / 256, B);
    k_phase3<<<g3, 256>>>(anc4, box4, labels, emean, estd, thr,
                          out_conf, out_delta, A, N, C);
}

// round 8
// speedup vs baseline: 7.1382x; 1.1140x over previous
#include <cuda_runtime.h>

#define TPB 128
#define APT 4                 // anchors per thread
#define CHUNK (TPB * APT)     // anchors per block = 512
#define NW   (TPB / 32)       // warps per block
#define SPLIT 2               // box-dimension split factor
#define MAXN 128              // max gt boxes per image supported
#define MAXB 16               // max batch

// Scratch (device globals; no allocation allowed)
__device__ unsigned long long g_partial[1 << 19];  // per-(b,n) per-chunk best keys
__device__ unsigned long long g_abest[1 << 21];    // per-(s,b,a) (iou, ~boxidx)
__device__ int                g_winner[1 << 20];   // per-(b,a) segment_max winner
__device__ float              g_miou[MAXB * MAXN]; // per-(b,n) max iou over anchors

// K1: grid (numChunks, SPLIT, B). Each block: 512 anchors x its half of the boxes.
//  - per-anchor best over its box half -> g_abest[(s*B+b)*A + a], key (iou<<32)|~n
//  - per-box warp/block best (tie -> lowest anchor) -> g_partial
//  - split 0 inits g_winner = -1
__global__ void __launch_bounds__(TPB)
k_phase1(const float4* __restrict__ anchors, const float4* __restrict__ bboxes,
         int A, int N, int numChunks, int B)
{
    __shared__ float4 sbox[MAXN];
    __shared__ float  sarea[MAXN];
    __shared__ unsigned long long swb[MAXN * NW];

    const int chunk = blockIdx.x, split = blockIdx.y, b = blockIdx.z;
    const int tid = threadIdx.x;
    const int lane = tid & 31, wid = tid >> 5;

    const int Nh   = (N + SPLIT - 1) / SPLIT;
    const int nofs = split * Nh;
    const int cnt  = (N - nofs < Nh) ? (N - nofs) : Nh;

    for (int n = tid; n < cnt; n += TPB) {
        float4 bb = bboxes[b * N + nofs + n];
        sbox[n] = bb;
        sarea[n] = (bb.z - bb.x) * (bb.w - bb.y);
    }
    __syncthreads();

    // Load APT anchors (stride TPB so within-warp anchor order == lane order)
    float ax1[APT], ay1[APT], ax2[APT], ay2[APT], areaA[APT];
    unsigned aidx[APT];
    bool avalid[APT];
    #pragma unroll
    for (int k = 0; k < APT; k++) {
        int a = chunk * CHUNK + k * TPB + tid;
        aidx[k] = (unsigned)a;
        avalid[k] = (a < A);
        if (avalid[k]) {
            float4 c = anchors[a];
            ax1[k] = c.x - c.z * 0.5f;  ay1[k] = c.y - c.w * 0.5f;
            ax2[k] = c.x + c.z * 0.5f;  ay2[k] = c.y + c.w * 0.5f;
            areaA[k] = (ax2[k] - ax1[k]) * (ay2[k] - ay1[k]);  // reference order
            if (split == 0) g_winner[(size_t)b * A + a] = -1;
        } else {
            // dummy: zero extent -> IoU exactly 0; index larger than every real
            // anchor so it never wins a tie-break.
            ax1[k] = 0.f; ay1[k] = 0.f; ax2[k] = 0.f; ay2[k] = 0.f;
            areaA[k] = 0.f;
        }
    }

    float bestI[APT];
    int   bestN[APT];
    #pragma unroll
    for (int k = 0; k < APT; k++) { bestI[k] = 0.0f; bestN[k] = nofs; }

    for (int n = 0; n < cnt; n++) {
        float4 bb = sbox[n];
        float sa = sarea[n];

        float iou[APT];
        #pragma unroll
        for (int k = 0; k < APT; k++) {
            float ltx = fmaxf(ax1[k], bb.x), lty = fmaxf(ay1[k], bb.y);
            float rbx = fminf(ax2[k], bb.z), rby = fminf(ay2[k], bb.w);
            float w = fmaxf(rbx - ltx, 0.f), h = fmaxf(rby - lty, 0.f);
            float inter = w * h;
            iou[k] = __fdividef(inter, areaA[k] + sa - inter);
        }

        // per-anchor running argmax (strict > = first occurrence within half)
        #pragma unroll
        for (int k = 0; k < APT; k++)
            if (iou[k] > bestI[k]) { bestI[k] = iou[k]; bestN[k] = nofs + n; }

        // merge the APT anchors (strict > keeps earlier = lower anchor index)
        float    mi = iou[0];
        unsigned wa = aidx[0];
        #pragma unroll
        for (int k = 1; k < APT; k++)
            if (iou[k] > mi) { mi = iou[k]; wa = aidx[k]; }

        // warp argmax over anchors for this box: max IoU (uint-monotone, IoU>=0),
        // tie -> min anchor index.
        unsigned u = __float_as_uint(mi);
        unsigned m = __reduce_max_sync(0xffffffffu, u);
        unsigned cand = (u == m) ? wa : 0xFFFFFFFFu;
        unsigned amin = __reduce_min_sync(0xffffffffu, cand);
        if (lane == 0)
            swb[n * NW + wid] =
                ((unsigned long long)m << 32) | (0xFFFFFFFFu - amin);
    }

    // per-anchor key: (iou<<32) | ~n  -> u64 max gives max iou, tie -> min n
    unsigned long long* ab = g_abest + ((size_t)split * B + b) * A;
    #pragma unroll
    for (int k = 0; k < APT; k++)
        if (avalid[k])
            ab[aidx[k]] =
                ((unsigned long long)__float_as_uint(bestI[k]) << 32) |
                (0xFFFFFFFFu - (unsigned)bestN[k]);

    __syncthreads();
    for (int n = tid; n < cnt; n += TPB) {
        unsigned long long best = swb[n * NW];
        #pragma unroll
        for (int w8 = 1; w8 < NW; w8++)
            if (swb[n * NW + w8] > best) best = swb[n * NW + w8];
        g_partial[((size_t)(b * N + nofs + n)) * numChunks + chunk] = best;
    }
}

// K2: reduce chunk partials per (b,n) -> max_iou_of_bbox + anchor argmax,
//     then segment_max scatter: winner[anchor] = max n claiming it.
__global__ void __launch_bounds__(64)
k_phase2(int A, int N, int numChunks)
{
    const int bn = blockIdx.x, tid = threadIdx.x;
    const unsigned long long* p = g_partial + (size_t)bn * numChunks;

    unsigned long long key = 0;
    for (int c = tid; c < numChunks; c += 64) {
        unsigned long long v = p[c];
        if (v > key) key = v;
    }
    __shared__ unsigned long long sred[2];
    #pragma unroll
    for (int off = 16; off; off >>= 1) {
        unsigned long long o = __shfl_down_sync(0xffffffffu, key, off);
        if (o > key) key = o;
    }
    if ((tid & 31) == 0) sred[tid >> 5] = key;
    __syncthreads();
    if (tid == 0) {
        if (sred[1] > key) key = sred[1];
        float miou = __uint_as_float((unsigned)(key >> 32));
        int   idx  = (int)(0xFFFFFFFFu - (unsigned)key);
        g_miou[bn] = miou;
        int b = bn / N, n = bn - b * N;
        atomicMax(&g_winner[(size_t)b * A + idx], n);
    }
}

// K3: epilogue per anchor: merge split abest keys, winner override, scores,
//     conf scatter, delta encode.
__global__ void __launch_bounds__(256)
k_phase3(const float4* __restrict__ anchors, const float4* __restrict__ bboxes,
         const int* __restrict__ labels,
         const float* __restrict__ enc_mean, const float* __restrict__ enc_std,
         const float* __restrict__ thr_ptr,
         float* __restrict__ out_conf, float4* __restrict__ out_delta,
         int A, int N, int C, int B)
{
    __shared__ float4 sbox[MAXN];
    __shared__ int    slab[MAXN];
    __shared__ float  smiou[MAXN];

    const int b = blockIdx.y, tid = threadIdx.x;
    for (int n = tid; n < N; n += 256) {
        sbox[n]  = bboxes[b * N + n];
        slab[n]  = labels[b * N + n];
        smiou[n] = g_miou[b * N + n];
    }
    __syncthreads();

    const int a = blockIdx.x * 256 + tid;
    if (a >= A) return;

    const float thr = __ldg(thr_ptr);

    // merge per-split per-anchor keys: max iou, tie -> min n (first occurrence)
    unsigned long long key = g_abest[(size_t)b * A + a];
    #pragma unroll
    for (int s = 1; s < SPLIT; s++) {
        unsigned long long k2 = g_abest[((size_t)s * B + b) * A + a];
        if (k2 > key) key = k2;
    }
    float miou = __uint_as_float((unsigned)(key >> 32));
    int   idx  = (int)(0xFFFFFFFFu - (unsigned)key);

    int w = g_winner[(size_t)b * A + a];
    if (w >= 0) { idx = w; miou = smiou[w]; }

    float den = fmaxf(smiou[idx], thr);
    if (miou < thr * 0.5f) miou = 0.f;
    float score = miou / den;

    int lab = slab[idx];
    if (lab <= 0) { score = 0.f; lab = 0; }

    const size_t base = (size_t)b * A + a;
    for (int c = 0; c < C; c++)
        out_conf[base * C + c] = (lab == c + 1) ? score : 0.f;

    float4 m   = sbox[idx];
    float4 anc = anchors[a];
    float mcx = (m.x + m.z) * 0.5f, mcy = (m.y + m.w) * 0.5f;
    float mw  = m.z - m.x,          mh  = m.w - m.y;
    float d0 = (mcx - anc.x) / anc.z;
    float d1 = (mcy - anc.y) / anc.w;
    float d2 = __logf(mw / anc.z);
    float d3 = __logf(mh / anc.w);
    float4 dv;
    dv.x = (d0 - __ldg(&enc_mean[0])) / __ldg(&enc_std[0]);
    dv.y = (d1 - __ldg(&enc_mean[1])) / __ldg(&enc_std[1]);
    dv.z = (d2 - __ldg(&enc_mean[2])) / __ldg(&enc_std[2]);
    dv.w = (d3 - __ldg(&enc_mean[3])) / __ldg(&enc_std[3]);
    out_delta[base] = dv;
}

extern "C" void kernel_launch(void* const* d_in, const int* in_sizes, int n_in,
                              void* d_out, int out_size)
{
    const float* anchors = (const float*)d_in[0];
    const int*   labels  = (const int*)d_in[1];
    const float* bboxes  = (const float*)d_in[2];
    const float* emean   = (const float*)d_in[3];
    const float* estd    = (const float*)d_in[4];
    const float* thr     = (const float*)d_in[5];

    const int A  = in_sizes[0] / 4;          // anchors [A,4]
    const int BN = in_sizes[1];              // labels [B,N]
    int B = out_size / (5 * A);
    if (B <= 0) B = 1;
    const int N = BN / B;
    const int C = (int)((long)out_size / ((long)B * A)) - 4;

    const float4* anc4 = (const float4*)anchors;
    const float4* box4 = (const float4*)bboxes;

    const int numChunks = (A + CHUNK - 1) / CHUNK;
    dim3 grid1(numChunks, SPLIT, B);
    k_phase1<<<grid1, TPB>>>(anc4, box4, A, N, numChunks, B);

    k_phase2<<<B * N, 64>>>(A, N, numChunks);

    float*  out_conf  = (float*)d_out;
    float4* out_delta = (float4*)((float*)d_out + (size_t)B * A * C);
    dim3 g3((A + 255) / 256, B);
    k_phase3<<<g3, 256>>>(anc4, box4, labels, emean, estd, thr,
                          out_conf, out_delta, A, N, C, B);
}

// round 9
// speedup vs baseline: 7.3595x; 1.0310x over previous
#include <cuda_runtime.h>

#define TPB 128
#define APT 4                 // anchors per thread (k_phase1)
#define CHUNK (TPB * APT)     // anchors per block = 512
#define NW   (TPB / 32)       // warps per block
#define MAXN 128              // max gt boxes per image supported
#define MAXB 16               // max batch

// Scratch (device globals; no allocation allowed)
__device__ unsigned long long g_partial[1 << 19];  // per-(b,n) per-chunk best keys
__device__ unsigned long long g_abest[1 << 20];    // per-(b,a) packed (iou, box idx)
__device__ int                g_winner[1 << 20];   // per-(b,a) segment_max winner
__device__ float              g_miou[MAXB * MAXN]; // per-(b,n) max iou over anchors

// K1: for each (batch, 512-anchor chunk): compute all IoUs vs N boxes once.
//  - per-anchor best (axis=1 argmax, strict > = first occurrence) -> g_abest
//  - per-box block-best (axis=0 argmax candidate, tie -> lowest anchor) -> g_partial
//  - init g_winner = -1
__global__ void __launch_bounds__(TPB)
k_phase1(const float4* __restrict__ anchors, const float4* __restrict__ bboxes,
         int A, int N, int numChunks)
{
    __shared__ float4 sbox[MAXN];
    __shared__ float  sarea[MAXN];
    __shared__ unsigned long long swb[MAXN * NW];

    const int b = blockIdx.y, chunk = blockIdx.x, tid = threadIdx.x;
    const int lane = tid & 31, wid = tid >> 5;

    for (int n = tid; n < N; n += TPB) {
        float4 bb = bboxes[b * N + n];
        sbox[n] = bb;
        sarea[n] = (bb.z - bb.x) * (bb.w - bb.y);
    }
    __syncthreads();

    // Load APT anchors (stride TPB so within-warp anchor order == lane order)
    float ax1[APT], ay1[APT], ax2[APT], ay2[APT], areaA[APT];
    unsigned aidx[APT];
    bool avalid[APT];
    #pragma unroll
    for (int k = 0; k < APT; k++) {
        int a = chunk * CHUNK + k * TPB + tid;
        aidx[k] = (unsigned)a;
        avalid[k] = (a < A);
        if (avalid[k]) {
            float4 c = anchors[a];
            ax1[k] = c.x - c.z * 0.5f;  ay1[k] = c.y - c.w * 0.5f;
            ax2[k] = c.x + c.z * 0.5f;  ay2[k] = c.y + c.w * 0.5f;
            areaA[k] = (ax2[k] - ax1[k]) * (ay2[k] - ay1[k]);  // reference order
            g_winner[(size_t)b * A + a] = -1;
        } else {
            // dummy: zero extent -> IoU exactly 0 vs any valid box; index larger
            // than every real anchor so it never wins a tie-break.
            ax1[k] = 0.f; ay1[k] = 0.f; ax2[k] = 0.f; ay2[k] = 0.f;
            areaA[k] = 0.f;
        }
    }

    float bestI[APT];
    int   bestN[APT];
    #pragma unroll
    for (int k = 0; k < APT; k++) { bestI[k] = 0.0f; bestN[k] = 0; }

    for (int n = 0; n < N; n++) {
        float4 bb = sbox[n];
        float sa = sarea[n];

        float iou[APT];
        #pragma unroll
        for (int k = 0; k < APT; k++) {
            float ltx = fmaxf(ax1[k], bb.x), lty = fmaxf(ay1[k], bb.y);
            float rbx = fminf(ax2[k], bb.z), rby = fminf(ay2[k], bb.w);
            float w = fmaxf(rbx - ltx, 0.f), h = fmaxf(rby - lty, 0.f);
            float inter = w * h;
            iou[k] = __fdividef(inter, areaA[k] + sa - inter);
        }

        // per-anchor running argmax (strict > = first occurrence)
        #pragma unroll
        for (int k = 0; k < APT; k++)
            if (iou[k] > bestI[k]) { bestI[k] = iou[k]; bestN[k] = n; }

        // merge the APT anchors (strict > keeps earlier = lower anchor index)
        float    mi = iou[0];
        unsigned wa = aidx[0];
        #pragma unroll
        for (int k = 1; k < APT; k++)
            if (iou[k] > mi) { mi = iou[k]; wa = aidx[k]; }

        // warp argmax over anchors for this box: max IoU (uint-monotone, IoU>=0),
        // tie -> min anchor index.
        unsigned u = __float_as_uint(mi);
        unsigned m = __reduce_max_sync(0xffffffffu, u);
        unsigned cand = (u == m) ? wa : 0xFFFFFFFFu;
        unsigned amin = __reduce_min_sync(0xffffffffu, cand);
        if (lane == 0)
            swb[n * NW + wid] =
                ((unsigned long long)m << 32) | (0xFFFFFFFFu - amin);
    }

    #pragma unroll
    for (int k = 0; k < APT; k++)
        if (avalid[k])
            g_abest[(size_t)b * A + aidx[k]] =
                ((unsigned long long)__float_as_uint(bestI[k]) << 32) |
                (unsigned)bestN[k];

    __syncthreads();
    for (int n = tid; n < N; n += TPB) {
        unsigned long long best = swb[n * NW];
        #pragma unroll
        for (int w8 = 1; w8 < NW; w8++)
            if (swb[n * NW + w8] > best) best = swb[n * NW + w8];
        g_partial[((size_t)(b * N + n)) * numChunks + chunk] = best;
    }
}

// K2: reduce chunk partials per (b,n) -> max_iou_of_bbox + anchor argmax,
//     then segment_max scatter: winner[anchor] = max n claiming it.
__global__ void __launch_bounds__(64)
k_phase2(int A, int N, int numChunks)
{
    const int bn = blockIdx.x, tid = threadIdx.x;
    const unsigned long long* p = g_partial + (size_t)bn * numChunks;

    unsigned long long key = 0;
    for (int c = tid; c < numChunks; c += 64) {
        unsigned long long v = p[c];
        if (v > key) key = v;
    }
    __shared__ unsigned long long sred[2];
    #pragma unroll
    for (int off = 16; off; off >>= 1) {
        unsigned long long o = __shfl_down_sync(0xffffffffu, key, off);
        if (o > key) key = o;
    }
    if ((tid & 31) == 0) sred[tid >> 5] = key;
    __syncthreads();
    if (tid == 0) {
        if (sred[1] > key) key = sred[1];
        float miou = __uint_as_float((unsigned)(key >> 32));
        int   idx  = (int)(0xFFFFFFFFu - (unsigned)key);
        g_miou[bn] = miou;
        int b = bn / N, n = bn - b * N;
        atomicMax(&g_winner[(size_t)b * A + idx], n);
    }
}

// K3: epilogue, 2 anchors per thread for MLP: winner override, scores,
//     conf scatter, delta encode.
__global__ void __launch_bounds__(256)
k_phase3(const float4* __restrict__ anchors, const float4* __restrict__ bboxes,
         const int* __restrict__ labels,
         const float* __restrict__ enc_mean, const float* __restrict__ enc_std,
         const float* __restrict__ thr_ptr,
         float* __restrict__ out_conf, float4* __restrict__ out_delta,
         int A, int N, int C)
{
    __shared__ float4 sbox[MAXN];
    __shared__ int    slab[MAXN];
    __shared__ float  smiou[MAXN];

    const int b = blockIdx.y, tid = threadIdx.x;
    for (int n = tid; n < N; n += 256) {
        sbox[n]  = bboxes[b * N + n];
        slab[n]  = labels[b * N + n];
        smiou[n] = g_miou[b * N + n];
    }
    __syncthreads();

    const float thr = __ldg(thr_ptr);
    const float em0 = __ldg(&enc_mean[0]), em1 = __ldg(&enc_mean[1]);
    const float em2 = __ldg(&enc_mean[2]), em3 = __ldg(&enc_mean[3]);
    const float rs0 = 1.0f / __ldg(&enc_std[0]), rs1 = 1.0f / __ldg(&enc_std[1]);
    const float rs2 = 1.0f / __ldg(&enc_std[2]), rs3 = 1.0f / __ldg(&enc_std[3]);

    #pragma unroll
    for (int h = 0; h < 2; h++) {
        const int a = blockIdx.x * 512 + h * 256 + tid;
        if (a >= A) continue;

        const size_t base = (size_t)b * A + a;
        unsigned long long ab = g_abest[base];
        int w = g_winner[base];
        float4 anc = __ldg(&anchors[a]);

        float miou = __uint_as_float((unsigned)(ab >> 32));
        int   idx  = (int)(unsigned)ab;
        if (w >= 0) { idx = w; miou = smiou[w]; }

        float den = fmaxf(smiou[idx], thr);
        if (miou < thr * 0.5f) miou = 0.f;
        float score = miou / den;

        int lab = slab[idx];
        if (lab <= 0) { score = 0.f; lab = 0; }

        for (int c = 0; c < C; c++)
            out_conf[base * C + c] = (lab == c + 1) ? score : 0.f;

        float4 m = sbox[idx];
        float mcx = (m.x + m.z) * 0.5f, mcy = (m.y + m.w) * 0.5f;
        float mw  = m.z - m.x,          mh  = m.w - m.y;
        float d0 = (mcx - anc.x) / anc.z;
        float d1 = (mcy - anc.y) / anc.w;
        float d2 = __logf(mw / anc.z);
        float d3 = __logf(mh / anc.w);
        float4 dv;
        dv.x = (d0 - em0) * rs0;
        dv.y = (d1 - em1) * rs1;
        dv.z = (d2 - em2) * rs2;
        dv.w = (d3 - em3) * rs3;
        out_delta[base] = dv;
    }
}

extern "C" void kernel_launch(void* const* d_in, const int* in_sizes, int n_in,
                              void* d_out, int out_size)
{
    const float* anchors = (const float*)d_in[0];
    const int*   labels  = (const int*)d_in[1];
    const float* bboxes  = (const float*)d_in[2];
    const float* emean   = (const float*)d_in[3];
    const float* estd    = (const float*)d_in[4];
    const float* thr     = (const float*)d_in[5];

    const int A  = in_sizes[0] / 4;          // anchors [A,4]
    const int BN = in_sizes[1];              // labels [B,N]
    int B = out_size / (5 * A);
    if (B <= 0) B = 1;
    const int N = BN / B;
    const int C = (int)((long)out_size / ((long)B * A)) - 4;

    const float4* anc4 = (const float4*)anchors;
    const float4* box4 = (const float4*)bboxes;

    const int numChunks = (A + CHUNK - 1) / CHUNK;
    dim3 grid1(numChunks, B);
    k_phase1<<<grid1, TPB>>>(anc4, box4, A, N, numChunks);

    k_phase2<<<B * N, 64>>>(A, N, numChunks);

    float*  out_conf  = (float*)d_out;
    float4* out_delta = (float4*)((float*)d_out + (size_t)B * A * C);
    dim3 g3((A + 511) / 512, B);
    k_phase3<<<g3, 256>>>(anc4, box4, labels, emean, estd, thr,
                          out_conf, out_delta, A, N, C);
}